// round 4
// baseline (speedup 1.0000x reference)
#include <cuda_runtime.h>
#include <cstdint>

#define BB 4096
#define DD 256
#define HH 1024
#define PP 10
#define NE (PP*BB*DD)      /* 10,485,760 */
#define NWORDS (NE/32)

// ---------------- device scratch (static globals; no runtime alloc) ----------
__device__ uint32_t g_ebits[4][NWORDS];
__device__ float    g_S[4][BB*HH];
__device__ float    g_W2t[DD*HH];
__device__ float    g_bias1[4*HH];
__device__ float    g_h[BB*HH];
__device__ float    g_z[BB*DD];
__device__ float    g_kf[BB*DD];
__device__ float    g_accz[BB*DD];
__device__ float    g_accd[BB];

struct Keys { unsigned int k[4][2]; };

// ---------------- Threefry-2x32 (bit-exact vs JAX) ----------------
__device__ __forceinline__ void tf_dev(unsigned int k0, unsigned int k1,
                                       unsigned int x0, unsigned int x1,
                                       unsigned int& o0, unsigned int& o1) {
    unsigned int k2 = k0 ^ k1 ^ 0x1BD11BDAu;
#define TFR(r) { x0 += x1; x1 = __funnelshift_l(x1, x1, r); x1 ^= x0; }
    x0 += k0; x1 += k1;          TFR(13) TFR(15) TFR(26) TFR(6)
    x0 += k1; x1 += k2 + 1u;     TFR(17) TFR(29) TFR(16) TFR(24)
    x0 += k2; x1 += k0 + 2u;     TFR(13) TFR(15) TFR(26) TFR(6)
    x0 += k0; x1 += k1 + 3u;     TFR(17) TFR(29) TFR(16) TFR(24)
    x0 += k1; x1 += k2 + 4u;     TFR(13) TFR(15) TFR(26) TFR(6)
    x0 += k2; x1 += k0 + 5u;
#undef TFR
    o0 = x0; o1 = x1;
}

static unsigned int h_rotl(unsigned int v, int r){ return (v<<r)|(v>>(32-r)); }
static void tf_host(unsigned int k0, unsigned int k1, unsigned int x0, unsigned int x1,
                    unsigned int& o0, unsigned int& o1) {
    unsigned int k2 = k0 ^ k1 ^ 0x1BD11BDAu;
#define TFR(r) { x0 += x1; x1 = h_rotl(x1, r); x1 ^= x0; }
    x0 += k0; x1 += k1;          TFR(13) TFR(15) TFR(26) TFR(6)
    x0 += k1; x1 += k2 + 1u;     TFR(17) TFR(29) TFR(16) TFR(24)
    x0 += k2; x1 += k0 + 2u;     TFR(13) TFR(15) TFR(26) TFR(6)
    x0 += k0; x1 += k1 + 3u;     TFR(17) TFR(29) TFR(16) TFR(24)
    x0 += k1; x1 += k2 + 4u;     TFR(13) TFR(15) TFR(26) TFR(6)
    x0 += k2; x1 += k0 + 5u;
#undef TFR
    o0 = x0; o1 = x1;
}

// ---------------- helpers ----------------
__device__ __forceinline__ unsigned int f2tf32(float f) {
    unsigned int u; asm("cvt.rna.tf32.f32 %0, %1;" : "=r"(u) : "f"(f)); return u;
}
__device__ __forceinline__ void mma8(float* d,
                                     unsigned int a0, unsigned int a1,
                                     unsigned int a2, unsigned int a3,
                                     unsigned int b0, unsigned int b1) {
    asm volatile(
        "mma.sync.aligned.m16n8k8.row.col.f32.tf32.tf32.f32 "
        "{%0,%1,%2,%3},{%4,%5,%6,%7},{%8,%9},{%0,%1,%2,%3};\n"
        : "+f"(d[0]), "+f"(d[1]), "+f"(d[2]), "+f"(d[3])
        : "r"(a0), "r"(a1), "r"(a2), "r"(a3), "r"(b0), "r"(b1));
}

// ---------------- prep: W2 transpose + per-stage bias ----------------
__global__ void prep_kernel(const float* __restrict__ W1,
                            const float* __restrict__ b1,
                            const float* __restrict__ W2) {
    int i = blockIdx.x * 256 + threadIdx.x;
    if (i < DD * HH) {
        int d = i >> 10, j = i & 1023;
        g_W2t[i] = W2[j * DD + d];
    }
    if (i < 4 * HH) {
        const float tv[4] = {0.0f, 0.5f, 0.5f, 1.0f};
        int st = i >> 10, j = i & 1023;
        g_bias1[i] = b1[j] + tv[st] * W1[256 * HH + j];
    }
}

// ---------------- RNG: partitionable-threefry counter mode -------------------
// word j of random_bits = out0 ^ out1 of threefry(k; hi=0, lo=j); bit = &1.
__global__ __launch_bounds__(256) void rng_kernel(Keys keys) {
    unsigned int j = blockIdx.x * 256u + threadIdx.x;   // element index < NE
    int st = blockIdx.y;
    unsigned int o0, o1;
    tf_dev(keys.k[st][0], keys.k[st][1], 0u, j, o0, o1);
    unsigned int word = __ballot_sync(0xffffffffu, (o0 ^ o1) & 1u);
    if ((threadIdx.x & 31u) == 0u) g_ebits[st][j >> 5] = word;
}

// ---------------- S kernel: S[st][r][j] = (1/P) sum_p (e@W1)_{rj} (e@W2^T)_{rj}
#define SK_SMEM ((2*256*72 + PP*64*8) * 4)   /* 167,936 bytes */

__global__ __launch_bounds__(256) void s_kernel(const float* __restrict__ W1) {
    extern __shared__ unsigned int sm[];
    unsigned int* sW1 = sm;
    unsigned int* sW2 = sm + 256 * 72;
    unsigned int* sE  = sm + 2 * 256 * 72;

    int tid = threadIdx.x;
    int r0 = blockIdx.x * 64;
    int j0 = blockIdx.y * 64;
    int st = blockIdx.z;

#pragma unroll
    for (int it = 0; it < 16; ++it) {
        int id  = tid + it * 256;
        int row = id >> 4;
        int c4  = (id & 15) * 4;
        float4 v = *(const float4*)(W1 + row * HH + j0 + c4);
        sW1[row*72 + c4+0] = f2tf32(v.x); sW1[row*72 + c4+1] = f2tf32(v.y);
        sW1[row*72 + c4+2] = f2tf32(v.z); sW1[row*72 + c4+3] = f2tf32(v.w);
        float4 w = *(const float4*)(g_W2t + row * HH + j0 + c4);
        sW2[row*72 + c4+0] = f2tf32(w.x); sW2[row*72 + c4+1] = f2tf32(w.y);
        sW2[row*72 + c4+2] = f2tf32(w.z); sW2[row*72 + c4+3] = f2tf32(w.w);
    }
    for (int id = tid; id < PP * 64 * 8; id += 256) {
        int p = id / (64 * 8);
        int rem = id - p * (64 * 8);
        int rr = rem >> 3, w = rem & 7;
        sE[id] = g_ebits[st][((p * BB + r0 + rr) << 3) + w];
    }
    __syncthreads();

    int lane = tid & 31, wid = tid >> 5;
    int wm = (wid & 3) * 16;
    int wn = (wid >> 2) * 32;
    int grp = lane >> 2, qd = lane & 3;

    float sacc[16];
#pragma unroll
    for (int i = 0; i < 16; ++i) sacc[i] = 0.0f;

    for (int p = 0; p < PP; ++p) {
        float u[16], g[16];
#pragma unroll
        for (int i = 0; i < 16; ++i) { u[i] = 0.0f; g[i] = 0.0f; }
        const unsigned int* eR0 = &sE[(p * 64 + wm + grp) * 8];
        const unsigned int* eR1 = &sE[(p * 64 + wm + grp + 8) * 8];
#pragma unroll 4
        for (int ks = 0; ks < 256; ks += 8) {
            unsigned int w0 = eR0[ks >> 5];
            unsigned int w1 = eR1[ks >> 5];
            int sh = (ks & 31) + qd;
            unsigned int a0 = 0x3F800000u | (((~(w0 >> sh)) & 1u) << 31);
            unsigned int a1 = 0x3F800000u | (((~(w1 >> sh)) & 1u) << 31);
            unsigned int a2 = 0x3F800000u | (((~(w0 >> (sh+4))) & 1u) << 31);
            unsigned int a3 = 0x3F800000u | (((~(w1 >> (sh+4))) & 1u) << 31);
#pragma unroll
            for (int t = 0; t < 4; ++t) {
                int n = wn + t * 8 + grp;
                mma8(&u[t*4], a0,a1,a2,a3, sW1[(ks+qd)*72 + n], sW1[(ks+qd+4)*72 + n]);
                mma8(&g[t*4], a0,a1,a2,a3, sW2[(ks+qd)*72 + n], sW2[(ks+qd+4)*72 + n]);
            }
        }
#pragma unroll
        for (int i = 0; i < 16; ++i) sacc[i] += u[i] * g[i];
    }

    const float inv = 1.0f / (float)PP;
    int rg = r0 + wm + grp;
#pragma unroll
    for (int t = 0; t < 4; ++t) {
        int col = j0 + wn + t * 8 + qd * 2;
        float2 v0 = make_float2(sacc[t*4+0]*inv, sacc[t*4+1]*inv);
        float2 v1 = make_float2(sacc[t*4+2]*inv, sacc[t*4+3]*inv);
        *(float2*)&g_S[st][rg * HH + col]       = v0;
        *(float2*)&g_S[st][(rg + 8) * HH + col] = v1;
    }
}

// ---------------- generic tf32 GEMM: C = act(A@B + bias) ----------------
template<int ACT>
__global__ __launch_bounds__(256) void gemm_kernel(const float* __restrict__ A,
                                                   const float* __restrict__ Bm,
                                                   const float* __restrict__ bias,
                                                   float* __restrict__ C,
                                                   int M, int N, int K) {
    __shared__ unsigned int sA[64 * 36];
    __shared__ unsigned int sB[32 * 72];
    int tid = threadIdx.x;
    int m0 = blockIdx.x * 64, n0 = blockIdx.y * 64;
    int lane = tid & 31, wid = tid >> 5;
    int wm = (wid & 3) * 16, wn = (wid >> 2) * 32;
    int grp = lane >> 2, qd = lane & 3;

    float acc[16];
#pragma unroll
    for (int i = 0; i < 16; ++i) acc[i] = 0.0f;

    for (int kc = 0; kc < K; kc += 32) {
        __syncthreads();
#pragma unroll
        for (int it = 0; it < 2; ++it) {
            int id = tid + it * 256;
            int rowA = id >> 3, cA = (id & 7) * 4;
            float4 va = *(const float4*)(A + (m0 + rowA) * K + kc + cA);
            sA[rowA*36 + cA+0] = f2tf32(va.x); sA[rowA*36 + cA+1] = f2tf32(va.y);
            sA[rowA*36 + cA+2] = f2tf32(va.z); sA[rowA*36 + cA+3] = f2tf32(va.w);
            int rowB = id >> 4, cB = (id & 15) * 4;
            float4 vb = *(const float4*)(Bm + (kc + rowB) * N + n0 + cB);
            sB[rowB*72 + cB+0] = f2tf32(vb.x); sB[rowB*72 + cB+1] = f2tf32(vb.y);
            sB[rowB*72 + cB+2] = f2tf32(vb.z); sB[rowB*72 + cB+3] = f2tf32(vb.w);
        }
        __syncthreads();
#pragma unroll
        for (int kq = 0; kq < 32; kq += 8) {
            unsigned int a0 = sA[(wm+grp  )*36 + kq+qd];
            unsigned int a1 = sA[(wm+grp+8)*36 + kq+qd];
            unsigned int a2 = sA[(wm+grp  )*36 + kq+qd+4];
            unsigned int a3 = sA[(wm+grp+8)*36 + kq+qd+4];
#pragma unroll
            for (int t = 0; t < 4; ++t) {
                int n = wn + t * 8 + grp;
                mma8(&acc[t*4], a0,a1,a2,a3, sB[(kq+qd)*72 + n], sB[(kq+qd+4)*72 + n]);
            }
        }
    }

    int rg = m0 + wm + grp;
#pragma unroll
    for (int t = 0; t < 4; ++t) {
        int col = n0 + wn + t * 8 + qd * 2;
#pragma unroll
        for (int half = 0; half < 2; ++half) {
            int r = rg + half * 8;
#pragma unroll
            for (int c = 0; c < 2; ++c) {
                float v = acc[t*4 + half*2 + c] + bias[col + c];
                if (ACT == 1) v = tanhf(v);
                C[r * N + col + c] = v;
            }
        }
    }
}

// ---------------- divergence accumulate: accd (+)= w * sum_j (1-h^2) S --------
__global__ __launch_bounds__(256) void div_acc_kernel(int st, float w) {
    int r = blockIdx.x;
    int tid = threadIdx.x;
    const float* hrow = g_h + r * HH;
    const float* Srow = &g_S[st][r * HH];
    float s = 0.0f;
    for (int j = tid; j < HH; j += 256) {
        float hv = hrow[j];
        s = fmaf(1.0f - hv * hv, Srow[j], s);
    }
#pragma unroll
    for (int o = 16; o > 0; o >>= 1) s += __shfl_down_sync(0xffffffffu, s, o);
    __shared__ float red[8];
    if ((tid & 31) == 0) red[tid >> 5] = s;
    __syncthreads();
    if (tid < 8) {
        s = red[tid];
#pragma unroll
        for (int o = 4; o > 0; o >>= 1) s += __shfl_down_sync(0xffu, s, o);
        if (tid == 0) g_accd[r] = (st == 0 ? 0.0f : g_accd[r]) + w * s;
    }
}

// ---------------- stage update: accz (+)= w*kf ; z_next = x + c*kf -----------
__global__ __launch_bounds__(256) void update_kernel(const float* __restrict__ x,
                                                     int st, float w, float c) {
    int i = blockIdx.x * 256 + threadIdx.x;
    float f = g_kf[i];
    g_accz[i] = (st == 0 ? 0.0f : g_accz[i]) + w * f;
    if (st < 3) g_z[i] = x[i] + c * f;
}

// ---------------- final: out = stack([y0, y1]) ----------------
__global__ __launch_bounds__(256) void final_kernel(const float* __restrict__ x,
                                                    float* __restrict__ out) {
    int i = blockIdx.x * 256 + threadIdx.x;
    const int half = BB * 257;
    if (i >= 2 * half) return;
    if (i < half) {
        int r = i / 257, d = i - r * 257;
        out[i] = (d < 256) ? x[r * DD + d] : 0.0f;
    } else {
        int j = i - half;
        int r = j / 257, d = j - r * 257;
        out[i] = (d < 256) ? x[r * DD + d] + g_accz[r * DD + d] * (1.0f / 6.0f)
                           : -g_accd[r] * (1.0f / 6.0f);
    }
}

// ---------------- launch ----------------
extern "C" void kernel_launch(void* const* d_in, const int* in_sizes, int n_in,
                              void* d_out, int out_size) {
    const float* x  = (const float*)d_in[0];
    const float* W1 = (const float*)d_in[1];
    const float* b1 = (const float*)d_in[2];
    const float* W2 = (const float*)d_in[3];
    const float* b2 = (const float*)d_in[4];
    float* out = (float*)d_out;
    (void)in_sizes; (void)n_in; (void)out_size;

    // Partitionable-threefry key derivation (host):
    //   fk_st = fold_in(key(42), st) = threefry((0,42), counter (0, st))
    //   split(fk_st, 2) foldlike: key_i = (out0, out1) of threefry(fk; (0, i))
    //   lower_bits uses key_1 (second element of split).
    Keys keys;
    for (unsigned int st = 0; st < 4; ++st) {
        unsigned int f0, f1;
        tf_host(0u, 42u, 0u, st, f0, f1);
        tf_host(f0, f1, 0u, 1u, keys.k[st][0], keys.k[st][1]);
    }

    float *gz, *gh, *gkf, *gbias;
    cudaGetSymbolAddress((void**)&gz,    g_z);
    cudaGetSymbolAddress((void**)&gh,    g_h);
    cudaGetSymbolAddress((void**)&gkf,   g_kf);
    cudaGetSymbolAddress((void**)&gbias, g_bias1);
    cudaFuncSetAttribute(s_kernel, cudaFuncAttributeMaxDynamicSharedMemorySize, SK_SMEM);

    prep_kernel<<<(DD * HH + 255) / 256, 256>>>(W1, b1, W2);
    rng_kernel<<<dim3(NE / 256, 4), 256>>>(keys);
    s_kernel<<<dim3(BB / 64, HH / 64, 4), 256, SK_SMEM>>>(W1);

    const float wst[4] = {1.0f, 2.0f, 2.0f, 1.0f};
    const float cst[4] = {0.5f, 0.5f, 1.0f, 0.0f};
    for (int st = 0; st < 4; ++st) {
        const float* Ain = (st == 0) ? x : gz;
        gemm_kernel<1><<<dim3(BB/64, HH/64), 256>>>(Ain, W1, gbias + st*HH,
                                                    gh, BB, HH, DD);
        gemm_kernel<0><<<dim3(BB/64, DD/64), 256>>>(gh, W2, b2,
                                                    gkf, BB, DD, HH);
        div_acc_kernel<<<BB, 256>>>(st, wst[st]);
        update_kernel<<<(BB*DD)/256, 256>>>(x, st, wst[st], cst[st]);
    }
    final_kernel<<<(2*BB*257 + 255)/256, 256>>>(x, out);
}

// round 5
// speedup vs baseline: 1.1482x; 1.1482x over previous
#include <cuda_runtime.h>
#include <cstdint>

#define BB 4096
#define DD 256
#define HH 1024
#define PP 10
#define NE (PP*BB*DD)

#define NWORDS (NE/32)

// ---------------- device scratch ----------------
__device__ uint32_t g_ebits[4][NWORDS];
__device__ float    g_S[4][BB*HH];
__device__ float    g_W2t[DD*HH];
__device__ float    g_bias1[4*HH];
__device__ float    g_h[BB*HH];
__device__ float    g_z[BB*DD];
__device__ float    g_accz[BB*DD];
__device__ float    g_accd[BB];

// ---------------- Threefry-2x32 ----------------
__device__ __forceinline__ void tf_dev(unsigned int k0, unsigned int k1,
                                       unsigned int x0, unsigned int x1,
                                       unsigned int& o0, unsigned int& o1) {
    unsigned int k2 = k0 ^ k1 ^ 0x1BD11BDAu;
#define TFR(r) { x0 += x1; x1 = __funnelshift_l(x1, x1, r); x1 ^= x0; }
    x0 += k0; x1 += k1;          TFR(13) TFR(15) TFR(26) TFR(6)
    x0 += k1; x1 += k2 + 1u;     TFR(17) TFR(29) TFR(16) TFR(24)
    x0 += k2; x1 += k0 + 2u;     TFR(13) TFR(15) TFR(26) TFR(6)
    x0 += k0; x1 += k1 + 3u;     TFR(17) TFR(29) TFR(16) TFR(24)
    x0 += k1; x1 += k2 + 4u;     TFR(13) TFR(15) TFR(26) TFR(6)
    x0 += k2; x1 += k0 + 5u;
#undef TFR
    o0 = x0; o1 = x1;
}

static unsigned int h_rotl(unsigned int v, int r){ return (v<<r)|(v>>(32-r)); }
static void tf_host(unsigned int k0, unsigned int k1, unsigned int x0, unsigned int x1,
                    unsigned int& o0, unsigned int& o1) {
    unsigned int k2 = k0 ^ k1 ^ 0x1BD11BDAu;
#define TFR(r) { x0 += x1; x1 = h_rotl(x1, r); x1 ^= x0; }
    x0 += k0; x1 += k1;          TFR(13) TFR(15) TFR(26) TFR(6)
    x0 += k1; x1 += k2 + 1u;     TFR(17) TFR(29) TFR(16) TFR(24)
    x0 += k2; x1 += k0 + 2u;     TFR(13) TFR(15) TFR(26) TFR(6)
    x0 += k0; x1 += k1 + 3u;     TFR(17) TFR(29) TFR(16) TFR(24)
    x0 += k1; x1 += k2 + 4u;     TFR(13) TFR(15) TFR(26) TFR(6)
    x0 += k2; x1 += k0 + 5u;
#undef TFR
    o0 = x0; o1 = x1;
}

// ---------------- helpers ----------------
__device__ __forceinline__ void mma8(float* d,
                                     unsigned int a0, unsigned int a1,
                                     unsigned int a2, unsigned int a3,
                                     unsigned int b0, unsigned int b1) {
    asm volatile(
        "mma.sync.aligned.m16n8k8.row.col.f32.tf32.tf32.f32 "
        "{%0,%1,%2,%3},{%4,%5,%6,%7},{%8,%9},{%0,%1,%2,%3};\n"
        : "+f"(d[0]), "+f"(d[1]), "+f"(d[2]), "+f"(d[3])
        : "r"(a0), "r"(a1), "r"(a2), "r"(a3), "r"(b0), "r"(b1));
}

// ---------------- prep: W2 transpose + per-stage bias + accd zero -------------
__global__ void prep_kernel(const float* __restrict__ W1,
                            const float* __restrict__ b1,
                            const float* __restrict__ W2) {
    int i = blockIdx.x * 256 + threadIdx.x;
    if (i < DD * HH) {
        int d = i >> 10, j = i & 1023;
        g_W2t[i] = W2[j * DD + d];
    }
    if (i < 4 * HH) {
        const float tv[4] = {0.0f, 0.5f, 0.5f, 1.0f};
        int st = i >> 10, j = i & 1023;
        g_bias1[i] = b1[j] + tv[st] * W1[256 * HH + j];
    }
    if (i < BB) g_accd[i] = 0.0f;
}

// ---------------- RNG (per stage): partitionable counter mode ----------------
__global__ __launch_bounds__(256) void rng_kernel(unsigned int k0, unsigned int k1,
                                                  int st) {
    unsigned int j = blockIdx.x * 256u + threadIdx.x;
    unsigned int o0, o1;
    tf_dev(k0, k1, 0u, j, o0, o1);
    unsigned int word = __ballot_sync(0xffffffffu, (o0 ^ o1) & 1u);
    if ((threadIdx.x & 31u) == 0u) g_ebits[st][j >> 5] = word;
}

// ---------------- S kernel (probe-paired) ------------------------------------
#define SK_SMEM ((2*256*72 + PP*64*8) * 4)

__global__ __launch_bounds__(256) void s_kernel(const float* __restrict__ W1) {
    extern __shared__ unsigned int sm[];
    unsigned int* sW1 = sm;
    unsigned int* sW2 = sm + 256 * 72;
    unsigned int* sE  = sm + 2 * 256 * 72;

    int tid = threadIdx.x;
    int r0 = blockIdx.x * 64;
    int j0 = blockIdx.y * 64;
    int st = blockIdx.z;

#pragma unroll
    for (int it = 0; it < 16; ++it) {
        int id  = tid + it * 256;
        int row = id >> 4;
        int c4  = (id & 15) * 4;
        float4 v = *(const float4*)(W1 + row * HH + j0 + c4);
        sW1[row*72 + c4+0] = __float_as_uint(v.x); sW1[row*72 + c4+1] = __float_as_uint(v.y);
        sW1[row*72 + c4+2] = __float_as_uint(v.z); sW1[row*72 + c4+3] = __float_as_uint(v.w);
        float4 w = *(const float4*)(g_W2t + row * HH + j0 + c4);
        sW2[row*72 + c4+0] = __float_as_uint(w.x); sW2[row*72 + c4+1] = __float_as_uint(w.y);
        sW2[row*72 + c4+2] = __float_as_uint(w.z); sW2[row*72 + c4+3] = __float_as_uint(w.w);
    }
    for (int id = tid; id < PP * 64 * 8; id += 256) {
        int p = id / (64 * 8);
        int rem = id - p * (64 * 8);
        int rr = rem >> 3, w = rem & 7;
        sE[id] = g_ebits[st][((p * BB + r0 + rr) << 3) + w];
    }
    __syncthreads();

    int lane = tid & 31, wid = tid >> 5;
    int wm = (wid & 3) * 16;
    int wn = (wid >> 2) * 32;
    int grp = lane >> 2, qd = lane & 3;

    float sacc[16];
#pragma unroll
    for (int i = 0; i < 16; ++i) sacc[i] = 0.0f;

    for (int pp = 0; pp < PP; pp += 2) {
        float u0[16], g0[16], u1[16], g1[16];
#pragma unroll
        for (int i = 0; i < 16; ++i) { u0[i]=0.f; g0[i]=0.f; u1[i]=0.f; g1[i]=0.f; }
        const unsigned int* e0a = &sE[(pp * 64 + wm + grp) * 8];
        const unsigned int* e0b = e0a + 64;
        const unsigned int* e1a = &sE[((pp + 1) * 64 + wm + grp) * 8];
        const unsigned int* e1b = e1a + 64;
#pragma unroll 4
        for (int ks = 0; ks < 256; ks += 8) {
            int wi = ks >> 5;
            int sh = (ks & 31) + qd;
            unsigned int w00 = e0a[wi], w01 = e0b[wi];
            unsigned int w10 = e1a[wi], w11 = e1b[wi];
            unsigned int A00 = 0x3F800000u | (((~(w00 >> sh)) & 1u) << 31);
            unsigned int A01 = 0x3F800000u | (((~(w01 >> sh)) & 1u) << 31);
            unsigned int A02 = 0x3F800000u | (((~(w00 >> (sh+4))) & 1u) << 31);
            unsigned int A03 = 0x3F800000u | (((~(w01 >> (sh+4))) & 1u) << 31);
            unsigned int A10 = 0x3F800000u | (((~(w10 >> sh)) & 1u) << 31);
            unsigned int A11 = 0x3F800000u | (((~(w11 >> sh)) & 1u) << 31);
            unsigned int A12 = 0x3F800000u | (((~(w10 >> (sh+4))) & 1u) << 31);
            unsigned int A13 = 0x3F800000u | (((~(w11 >> (sh+4))) & 1u) << 31);
#pragma unroll
            for (int t = 0; t < 4; ++t) {
                int n = wn + t * 8 + grp;
                unsigned int b10 = sW1[(ks+qd)*72 + n], b11 = sW1[(ks+qd+4)*72 + n];
                unsigned int b20 = sW2[(ks+qd)*72 + n], b21 = sW2[(ks+qd+4)*72 + n];
                mma8(&u0[t*4], A00,A01,A02,A03, b10,b11);
                mma8(&u1[t*4], A10,A11,A12,A13, b10,b11);
                mma8(&g0[t*4], A00,A01,A02,A03, b20,b21);
                mma8(&g1[t*4], A10,A11,A12,A13, b20,b21);
            }
        }
#pragma unroll
        for (int i = 0; i < 16; ++i) sacc[i] += u0[i]*g0[i] + u1[i]*g1[i];
    }

    const float inv = 1.0f / (float)PP;
    int rg = r0 + wm + grp;
#pragma unroll
    for (int t = 0; t < 4; ++t) {
        int col = j0 + wn + t * 8 + qd * 2;
        float2 v0 = make_float2(sacc[t*4+0]*inv, sacc[t*4+1]*inv);
        float2 v1 = make_float2(sacc[t*4+2]*inv, sacc[t*4+3]*inv);
        *(float2*)&g_S[st][rg * HH + col]       = v0;
        *(float2*)&g_S[st][(rg + 8) * HH + col] = v1;
    }
}

// ---------------- fused main-chain GEMM (128x128x32, double-buffered) --------
// MODE 1: C=tanh(A@W1+bias) -> g_h, + divergence partial into accd (weight wq)
// MODE 0: f=A@W2+b2 ; accz (+)= wq*f ; z = x + cq*f (st<3)
#define GEMM_SMEM ((2*128*36 + 2*32*136) * 4 + 128 * 4)

template<int MODE>
__global__ __launch_bounds__(256) void gemm_kernel(
    const float* __restrict__ A, const float* __restrict__ Bm,
    const float* __restrict__ bias, float* __restrict__ Hout,
    const float* __restrict__ S, float* __restrict__ accd,
    const float* __restrict__ x, float* __restrict__ accz, float* __restrict__ z,
    int N, int K, int st, float wq, float cq)
{
    extern __shared__ unsigned int dsm[];
    unsigned int* sA = dsm;                          // 2 x [128][36]
    unsigned int* sB = dsm + 2 * 128 * 36;           // 2 x [32][136]
    float* rowsum = (float*)(dsm + 2*128*36 + 2*32*136);

    int tid = threadIdx.x, lane = tid & 31, wid = tid >> 5;
    int m0 = blockIdx.x * 128, n0 = blockIdx.y * 128;
    int wm = (wid & 1) * 64, wn = (wid >> 1) * 32;
    int grp = lane >> 2, qd = lane & 3;

    if (MODE == 1 && tid < 128) rowsum[tid] = 0.0f;

    float acc[4][4][4];
#pragma unroll
    for (int a = 0; a < 4; ++a)
#pragma unroll
        for (int b = 0; b < 4; ++b)
#pragma unroll
            for (int cc = 0; cc < 4; ++cc) acc[a][b][cc] = 0.0f;

    float4 va[4], vb[4];
    int nch = K / 32;

#define LOADG(KC) { \
    _Pragma("unroll") \
    for (int it = 0; it < 4; ++it) { \
        int f = tid + it * 256; \
        int ra = f >> 3, ca = (f & 7) * 4; \
        va[it] = *(const float4*)(A + (size_t)(m0 + ra) * K + (KC) + ca); \
        int rb = f >> 5, cb = (f & 31) * 4; \
        vb[it] = *(const float4*)(Bm + (size_t)((KC) + rb) * N + n0 + cb); \
    } }

#define STOREB(BUF) { \
    unsigned int* dA = sA + (BUF) * (128 * 36); \
    unsigned int* dB = sB + (BUF) * (32 * 136); \
    _Pragma("unroll") \
    for (int it = 0; it < 4; ++it) { \
        int f = tid + it * 256; \
        int ra = f >> 3, ca = (f & 7) * 4; \
        *(float4*)&dA[ra * 36 + ca] = va[it]; \
        int rb = f >> 5, cb = (f & 31) * 4; \
        *(float4*)&dB[rb * 136 + cb] = vb[it]; \
    } }

    LOADG(0); STOREB(0); __syncthreads();

    for (int ch = 0; ch < nch; ++ch) {
        if (ch + 1 < nch) LOADG((ch + 1) * 32);
        const unsigned int* bA = sA + (ch & 1) * (128 * 36);
        const unsigned int* bB = sB + (ch & 1) * (32 * 136);
#pragma unroll
        for (int kq = 0; kq < 32; kq += 8) {
            unsigned int ar[4][4];
#pragma unroll
            for (int mi = 0; mi < 4; ++mi) {
                int r = wm + mi * 16 + grp;
                ar[mi][0] = bA[r * 36 + kq + qd];
                ar[mi][1] = bA[(r + 8) * 36 + kq + qd];
                ar[mi][2] = bA[r * 36 + kq + qd + 4];
                ar[mi][3] = bA[(r + 8) * 36 + kq + qd + 4];
            }
            unsigned int br[4][2];
#pragma unroll
            for (int ni = 0; ni < 4; ++ni) {
                int n = wn + ni * 8 + grp;
                br[ni][0] = bB[(kq + qd) * 136 + n];
                br[ni][1] = bB[(kq + qd + 4) * 136 + n];
            }
#pragma unroll
            for (int mi = 0; mi < 4; ++mi)
#pragma unroll
                for (int ni = 0; ni < 4; ++ni)
                    mma8(acc[mi][ni], ar[mi][0],ar[mi][1],ar[mi][2],ar[mi][3],
                         br[ni][0], br[ni][1]);
        }
        if (ch + 1 < nch) STOREB((ch + 1) & 1);
        __syncthreads();
    }
#undef LOADG
#undef STOREB

    if (MODE == 1) {
#pragma unroll
        for (int mi = 0; mi < 4; ++mi)
#pragma unroll
            for (int half = 0; half < 2; ++half) {
                int r = m0 + wm + mi * 16 + grp + half * 8;
                float ds = 0.0f;
#pragma unroll
                for (int ni = 0; ni < 4; ++ni) {
                    int col = n0 + wn + ni * 8 + qd * 2;
                    float v0 = tanhf(acc[mi][ni][half*2+0] + bias[col]);
                    float v1 = tanhf(acc[mi][ni][half*2+1] + bias[col+1]);
                    *(float2*)&Hout[(size_t)r * HH + col] = make_float2(v0, v1);
                    float2 sv = *(const float2*)&S[(size_t)r * HH + col];
                    ds = fmaf(1.0f - v0*v0, sv.x, ds);
                    ds = fmaf(1.0f - v1*v1, sv.y, ds);
                }
                ds += __shfl_xor_sync(0xffffffffu, ds, 1);
                ds += __shfl_xor_sync(0xffffffffu, ds, 2);
                if (qd == 0) atomicAdd(&rowsum[wm + mi*16 + grp + half*8], ds);
            }
        __syncthreads();
        if (tid < 128) atomicAdd(&accd[m0 + tid], wq * rowsum[tid]);
    } else {
#pragma unroll
        for (int mi = 0; mi < 4; ++mi)
#pragma unroll
            for (int half = 0; half < 2; ++half) {
                int r = m0 + wm + mi * 16 + grp + half * 8;
#pragma unroll
                for (int ni = 0; ni < 4; ++ni) {
                    int col = n0 + wn + ni * 8 + qd * 2;
                    float f0 = acc[mi][ni][half*2+0] + bias[col];
                    float f1 = acc[mi][ni][half*2+1] + bias[col+1];
                    size_t idx = (size_t)r * DD + col;
                    float2 az;
                    if (st == 0) az = make_float2(0.f, 0.f);
                    else az = *(float2*)&accz[idx];
                    az.x += wq * f0; az.y += wq * f1;
                    *(float2*)&accz[idx] = az;
                    if (st < 3) {
                        float2 xx = *(const float2*)&x[idx];
                        *(float2*)&z[idx] = make_float2(xx.x + cq*f0, xx.y + cq*f1);
                    }
                }
            }
    }
}

// ---------------- final: out = stack([y0, y1]) ----------------
__global__ __launch_bounds__(256) void final_kernel(const float* __restrict__ x,
                                                    float* __restrict__ out) {
    int i = blockIdx.x * 256 + threadIdx.x;
    const int half = BB * 257;
    if (i >= 2 * half) return;
    if (i < half) {
        int r = i / 257, d = i - r * 257;
        out[i] = (d < 256) ? x[r * DD + d] : 0.0f;
    } else {
        int j = i - half;
        int r = j / 257, d = j - r * 257;
        out[i] = (d < 256) ? x[r * DD + d] + g_accz[r * DD + d] * (1.0f / 6.0f)
                           : -g_accd[r] * (1.0f / 6.0f);
    }
}

// ---------------- launch ----------------
extern "C" void kernel_launch(void* const* d_in, const int* in_sizes, int n_in,
                              void* d_out, int out_size) {
    const float* x  = (const float*)d_in[0];
    const float* W1 = (const float*)d_in[1];
    const float* b1 = (const float*)d_in[2];
    const float* W2 = (const float*)d_in[3];
    const float* b2 = (const float*)d_in[4];
    float* out = (float*)d_out;
    (void)in_sizes; (void)n_in; (void)out_size;

    unsigned int kk[4][2];
    for (unsigned int st = 0; st < 4; ++st) {
        unsigned int f0, f1;
        tf_host(0u, 42u, 0u, st, f0, f1);
        tf_host(f0, f1, 0u, 1u, kk[st][0], kk[st][1]);
    }

    float *gz, *gh, *gbias, *gS, *gaccd, *gaccz;
    cudaGetSymbolAddress((void**)&gz,    g_z);
    cudaGetSymbolAddress((void**)&gh,    g_h);
    cudaGetSymbolAddress((void**)&gbias, g_bias1);
    cudaGetSymbolAddress((void**)&gS,    g_S);
    cudaGetSymbolAddress((void**)&gaccd, g_accd);
    cudaGetSymbolAddress((void**)&gaccz, g_accz);

    cudaFuncSetAttribute(s_kernel, cudaFuncAttributeMaxDynamicSharedMemorySize, SK_SMEM);
    cudaFuncSetAttribute(gemm_kernel<0>, cudaFuncAttributeMaxDynamicSharedMemorySize, GEMM_SMEM);
    cudaFuncSetAttribute(gemm_kernel<1>, cudaFuncAttributeMaxDynamicSharedMemorySize, GEMM_SMEM);

    prep_kernel<<<(DD * HH + 255) / 256, 256>>>(W1, b1, W2);
    for (int st = 0; st < 4; ++st)
        rng_kernel<<<NE / 256, 256>>>(kk[st][0], kk[st][1], st);
    s_kernel<<<dim3(BB / 64, HH / 64, 4), 256, SK_SMEM>>>(W1);

    const float wst[4] = {1.0f, 2.0f, 2.0f, 1.0f};
    const float cst[4] = {0.5f, 0.5f, 1.0f, 0.0f};
    for (int st = 0; st < 4; ++st) {
        const float* Ain = (st == 0) ? x : gz;
        gemm_kernel<1><<<dim3(BB/128, HH/128), 256, GEMM_SMEM>>>(
            Ain, W1, gbias + st*HH, gh,
            gS + (size_t)st * BB * HH, gaccd,
            nullptr, nullptr, nullptr,
            HH, DD, st, wst[st], cst[st]);
        gemm_kernel<0><<<dim3(BB/128, DD/128), 256, GEMM_SMEM>>>(
            gh, W2, b2, nullptr,
            nullptr, nullptr,
            x, gaccz, gz,
            DD, HH, st, wst[st], cst[st]);
    }
    final_kernel<<<(2*BB*257 + 255)/256, 256>>>(x, out);
}

// round 6
// speedup vs baseline: 1.7035x; 1.4836x over previous
#include <cuda_runtime.h>
#include <cuda_fp16.h>
#include <cstdint>

#define BB 4096
#define DD 256
#define HH 1024
#define PP 10
#define NE (PP*BB*DD)
#define NWORDS (NE/32)

// ---------------- device scratch ----------------
__device__ uint32_t g_ebits[4][NWORDS];
__device__ float    g_S[4][BB*HH];
__device__ float    g_W2t[DD*HH];
__device__ float    g_bias1[4*HH];
__device__ float    g_h[BB*HH];
__device__ float    g_z[BB*DD];
__device__ float    g_accz[BB*DD];
__device__ float    g_accd[BB];

// ---------------- Threefry-2x32 ----------------
__device__ __forceinline__ void tf_dev(unsigned int k0, unsigned int k1,
                                       unsigned int x0, unsigned int x1,
                                       unsigned int& o0, unsigned int& o1) {
    unsigned int k2 = k0 ^ k1 ^ 0x1BD11BDAu;
#define TFR(r) { x0 += x1; x1 = __funnelshift_l(x1, x1, r); x1 ^= x0; }
    x0 += k0; x1 += k1;          TFR(13) TFR(15) TFR(26) TFR(6)
    x0 += k1; x1 += k2 + 1u;     TFR(17) TFR(29) TFR(16) TFR(24)
    x0 += k2; x1 += k0 + 2u;     TFR(13) TFR(15) TFR(26) TFR(6)
    x0 += k0; x1 += k1 + 3u;     TFR(17) TFR(29) TFR(16) TFR(24)
    x0 += k1; x1 += k2 + 4u;     TFR(13) TFR(15) TFR(26) TFR(6)
    x0 += k2; x1 += k0 + 5u;
#undef TFR
    o0 = x0; o1 = x1;
}

static unsigned int h_rotl(unsigned int v, int r){ return (v<<r)|(v>>(32-r)); }
static void tf_host(unsigned int k0, unsigned int k1, unsigned int x0, unsigned int x1,
                    unsigned int& o0, unsigned int& o1) {
    unsigned int k2 = k0 ^ k1 ^ 0x1BD11BDAu;
#define TFR(r) { x0 += x1; x1 = h_rotl(x1, r); x1 ^= x0; }
    x0 += k0; x1 += k1;          TFR(13) TFR(15) TFR(26) TFR(6)
    x0 += k1; x1 += k2 + 1u;     TFR(17) TFR(29) TFR(16) TFR(24)
    x0 += k2; x1 += k0 + 2u;     TFR(13) TFR(15) TFR(26) TFR(6)
    x0 += k0; x1 += k1 + 3u;     TFR(17) TFR(29) TFR(16) TFR(24)
    x0 += k1; x1 += k2 + 4u;     TFR(13) TFR(15) TFR(26) TFR(6)
    x0 += k2; x1 += k0 + 5u;
#undef TFR
    o0 = x0; o1 = x1;
}

// ---------------- mma helpers ----------------
__device__ __forceinline__ void mma8(float* d,
                                     unsigned int a0, unsigned int a1,
                                     unsigned int a2, unsigned int a3,
                                     unsigned int b0, unsigned int b1) {
    asm volatile(
        "mma.sync.aligned.m16n8k8.row.col.f32.tf32.tf32.f32 "
        "{%0,%1,%2,%3},{%4,%5,%6,%7},{%8,%9},{%0,%1,%2,%3};\n"
        : "+f"(d[0]), "+f"(d[1]), "+f"(d[2]), "+f"(d[3])
        : "r"(a0), "r"(a1), "r"(a2), "r"(a3), "r"(b0), "r"(b1));
}
__device__ __forceinline__ void mma16h(float* d,
                                       unsigned int a0, unsigned int a1,
                                       unsigned int a2, unsigned int a3,
                                       unsigned int b0, unsigned int b1) {
    asm volatile(
        "mma.sync.aligned.m16n8k16.row.col.f32.f16.f16.f32 "
        "{%0,%1,%2,%3},{%4,%5,%6,%7},{%8,%9},{%0,%1,%2,%3};\n"
        : "+f"(d[0]), "+f"(d[1]), "+f"(d[2]), "+f"(d[3])
        : "r"(a0), "r"(a1), "r"(a2), "r"(a3), "r"(b0), "r"(b1));
}
// pack 2 sign-bits (bit0 -> low half k, bit1 -> high half k+1) into ±1 half2
__device__ __forceinline__ unsigned int pk(unsigned int t) {
    return 0x3C003C00u | ((t & 1u) << 15) | ((t & 2u) << 30);
}
__device__ __forceinline__ unsigned int h2pack(float lo, float hi) {
    __half2 h = __floats2half2_rn(lo, hi);
    return *(unsigned int*)&h;
}

// ---------------- prep: W2 transpose + per-stage bias + accd zero -------------
__global__ void prep_kernel(const float* __restrict__ W1,
                            const float* __restrict__ b1,
                            const float* __restrict__ W2) {
    int i = blockIdx.x * 256 + threadIdx.x;
    if (i < DD * HH) {
        int d = i >> 10, j = i & 1023;
        g_W2t[i] = W2[j * DD + d];
    }
    if (i < 4 * HH) {
        const float tv[4] = {0.0f, 0.5f, 0.5f, 1.0f};
        int st = i >> 10, j = i & 1023;
        g_bias1[i] = b1[j] + tv[st] * W1[256 * HH + j];
    }
    if (i < BB) g_accd[i] = 0.0f;
}

// ---------------- RNG (per stage): partitionable counter mode ----------------
__global__ __launch_bounds__(256) void rng_kernel(unsigned int k0, unsigned int k1,
                                                  int st) {
    unsigned int j = blockIdx.x * 256u + threadIdx.x;
    unsigned int o0, o1;
    tf_dev(k0, k1, 0u, j, o0, o1);
    unsigned int word = __ballot_sync(0xffffffffu, (o0 ^ o1) & 1u);
    if ((threadIdx.x & 31u) == 0u) g_ebits[st][j >> 5] = word;
}

// ---------------- S kernel (fp16 m16n8k16, probe-paired) ---------------------
// smem: sW1h/sW2h as [128 kpairs][64+8 pad] half2 words; sE packed bits.
#define SK_SMEM ((2*128*72 + PP*64*8) * 4)   /* 94,208 bytes */

__global__ __launch_bounds__(256, 2) void s_kernel(const float* __restrict__ W1) {
    extern __shared__ unsigned int sm[];
    unsigned int* sW1h = sm;                  // [128][72]
    unsigned int* sW2h = sm + 128 * 72;       // [128][72]
    unsigned int* sE   = sm + 2 * 128 * 72;   // [PP][64][8]

    int tid = threadIdx.x;
    int r0 = blockIdx.x * 64;
    int j0 = blockIdx.y * 64;
    int st = blockIdx.z;

    // load W tiles: pair consecutive k rows into half2 words
#pragma unroll
    for (int it = 0; it < 8; ++it) {
        int id = tid + it * 256;        // 0..2047
        int kp = id >> 4;               // 0..127
        int c4 = (id & 15) * 4;
        const float* p0 = W1 + (size_t)(2*kp)   * HH + j0 + c4;
        const float* p1 = W1 + (size_t)(2*kp+1) * HH + j0 + c4;
        float4 v0 = *(const float4*)p0, v1 = *(const float4*)p1;
        sW1h[kp*72 + c4+0] = h2pack(v0.x, v1.x);
        sW1h[kp*72 + c4+1] = h2pack(v0.y, v1.y);
        sW1h[kp*72 + c4+2] = h2pack(v0.z, v1.z);
        sW1h[kp*72 + c4+3] = h2pack(v0.w, v1.w);
        const float* q0 = g_W2t + (size_t)(2*kp)   * HH + j0 + c4;
        const float* q1 = g_W2t + (size_t)(2*kp+1) * HH + j0 + c4;
        float4 w0 = *(const float4*)q0, w1 = *(const float4*)q1;
        sW2h[kp*72 + c4+0] = h2pack(w0.x, w1.x);
        sW2h[kp*72 + c4+1] = h2pack(w0.y, w1.y);
        sW2h[kp*72 + c4+2] = h2pack(w0.z, w1.z);
        sW2h[kp*72 + c4+3] = h2pack(w0.w, w1.w);
    }
    for (int id = tid; id < PP * 64 * 8; id += 256) {
        int p = id / (64 * 8);
        int rem = id - p * (64 * 8);
        int rr = rem >> 3, w = rem & 7;
        sE[id] = g_ebits[st][((p * BB + r0 + rr) << 3) + w];
    }
    __syncthreads();

    int lane = tid & 31, wid = tid >> 5;
    int wm = (wid & 3) * 16;
    int wn = (wid >> 2) * 32;
    int grp = lane >> 2, qd = lane & 3;

    float sacc[16];
#pragma unroll
    for (int i = 0; i < 16; ++i) sacc[i] = 0.0f;

    for (int pp = 0; pp < PP; pp += 2) {
        float u0[16], g0[16], u1[16], g1[16];
#pragma unroll
        for (int i = 0; i < 16; ++i) { u0[i]=0.f; g0[i]=0.f; u1[i]=0.f; g1[i]=0.f; }
        const unsigned int* e0a = &sE[(pp * 64 + wm + grp) * 8];
        const unsigned int* e0b = e0a + 64;
        const unsigned int* e1a = &sE[((pp + 1) * 64 + wm + grp) * 8];
        const unsigned int* e1b = e1a + 64;
#pragma unroll 4
        for (int ks = 0; ks < 256; ks += 16) {
            int wi = ks >> 5;
            int sh = (ks & 31) + 2 * qd;
            unsigned int t00 = ~(e0a[wi] >> sh);   // probe0, row grp
            unsigned int t01 = ~(e0b[wi] >> sh);   // probe0, row grp+8
            unsigned int t10 = ~(e1a[wi] >> sh);
            unsigned int t11 = ~(e1b[wi] >> sh);
            unsigned int A00 = pk(t00), A01 = pk(t01);
            unsigned int A02 = pk(t00 >> 8), A03 = pk(t01 >> 8);
            unsigned int A10 = pk(t10), A11 = pk(t11);
            unsigned int A12 = pk(t10 >> 8), A13 = pk(t11 >> 8);
            int kp0 = (ks >> 1) + qd;
#pragma unroll
            for (int t = 0; t < 4; ++t) {
                int n = wn + t * 8 + grp;
                unsigned int b10 = sW1h[kp0*72 + n], b11 = sW1h[(kp0+4)*72 + n];
                unsigned int b20 = sW2h[kp0*72 + n], b21 = sW2h[(kp0+4)*72 + n];
                mma16h(&u0[t*4], A00,A01,A02,A03, b10,b11);
                mma16h(&u1[t*4], A10,A11,A12,A13, b10,b11);
                mma16h(&g0[t*4], A00,A01,A02,A03, b20,b21);
                mma16h(&g1[t*4], A10,A11,A12,A13, b20,b21);
            }
        }
#pragma unroll
        for (int i = 0; i < 16; ++i) sacc[i] += u0[i]*g0[i] + u1[i]*g1[i];
    }

    const float inv = 1.0f / (float)PP;
    int rg = r0 + wm + grp;
#pragma unroll
    for (int t = 0; t < 4; ++t) {
        int col = j0 + wn + t * 8 + qd * 2;
        float2 v0 = make_float2(sacc[t*4+0]*inv, sacc[t*4+1]*inv);
        float2 v1 = make_float2(sacc[t*4+2]*inv, sacc[t*4+3]*inv);
        *(float2*)&g_S[st][rg * HH + col]       = v0;
        *(float2*)&g_S[st][(rg + 8) * HH + col] = v1;
    }
}

// ---------------- fused main-chain GEMM (tf32, 128x128x32, double-buffered) --
#define GEMM_SMEM ((2*128*36 + 2*32*136) * 4 + 128 * 4)

template<int MODE>
__global__ __launch_bounds__(256) void gemm_kernel(
    const float* __restrict__ A, const float* __restrict__ Bm,
    const float* __restrict__ bias, float* __restrict__ Hout,
    const float* __restrict__ S, float* __restrict__ accd,
    const float* __restrict__ x, float* __restrict__ accz, float* __restrict__ z,
    int N, int K, int st, float wq, float cq)
{
    extern __shared__ unsigned int dsm[];
    unsigned int* sA = dsm;
    unsigned int* sB = dsm + 2 * 128 * 36;
    float* rowsum = (float*)(dsm + 2*128*36 + 2*32*136);

    int tid = threadIdx.x, lane = tid & 31, wid = tid >> 5;
    int m0 = blockIdx.x * 128, n0 = blockIdx.y * 128;
    int wm = (wid & 1) * 64, wn = (wid >> 1) * 32;
    int grp = lane >> 2, qd = lane & 3;

    if (MODE == 1 && tid < 128) rowsum[tid] = 0.0f;

    float acc[4][4][4];
#pragma unroll
    for (int a = 0; a < 4; ++a)
#pragma unroll
        for (int b = 0; b < 4; ++b)
#pragma unroll
            for (int cc = 0; cc < 4; ++cc) acc[a][b][cc] = 0.0f;

    float4 va[4], vb[4];
    int nch = K / 32;

#define LOADG(KC) { \
    _Pragma("unroll") \
    for (int it = 0; it < 4; ++it) { \
        int f = tid + it * 256; \
        int ra = f >> 3, ca = (f & 7) * 4; \
        va[it] = *(const float4*)(A + (size_t)(m0 + ra) * K + (KC) + ca); \
        int rb = f >> 5, cb = (f & 31) * 4; \
        vb[it] = *(const float4*)(Bm + (size_t)((KC) + rb) * N + n0 + cb); \
    } }

#define STOREB(BUF) { \
    unsigned int* dA = sA + (BUF) * (128 * 36); \
    unsigned int* dB = sB + (BUF) * (32 * 136); \
    _Pragma("unroll") \
    for (int it = 0; it < 4; ++it) { \
        int f = tid + it * 256; \
        int ra = f >> 3, ca = (f & 7) * 4; \
        *(float4*)&dA[ra * 36 + ca] = va[it]; \
        int rb = f >> 5, cb = (f & 31) * 4; \
        *(float4*)&dB[rb * 136 + cb] = vb[it]; \
    } }

    LOADG(0); STOREB(0); __syncthreads();

    for (int ch = 0; ch < nch; ++ch) {
        if (ch + 1 < nch) LOADG((ch + 1) * 32);
        const unsigned int* bA = sA + (ch & 1) * (128 * 36);
        const unsigned int* bB = sB + (ch & 1) * (32 * 136);
#pragma unroll
        for (int kq = 0; kq < 32; kq += 8) {
            unsigned int ar[4][4];
#pragma unroll
            for (int mi = 0; mi < 4; ++mi) {
                int r = wm + mi * 16 + grp;
                ar[mi][0] = bA[r * 36 + kq + qd];
                ar[mi][1] = bA[(r + 8) * 36 + kq + qd];
                ar[mi][2] = bA[r * 36 + kq + qd + 4];
                ar[mi][3] = bA[(r + 8) * 36 + kq + qd + 4];
            }
            unsigned int br[4][2];
#pragma unroll
            for (int ni = 0; ni < 4; ++ni) {
                int n = wn + ni * 8 + grp;
                br[ni][0] = bB[(kq + qd) * 136 + n];
                br[ni][1] = bB[(kq + qd + 4) * 136 + n];
            }
#pragma unroll
            for (int mi = 0; mi < 4; ++mi)
#pragma unroll
                for (int ni = 0; ni < 4; ++ni)
                    mma8(acc[mi][ni], ar[mi][0],ar[mi][1],ar[mi][2],ar[mi][3],
                         br[ni][0], br[ni][1]);
        }
        if (ch + 1 < nch) STOREB((ch + 1) & 1);
        __syncthreads();
    }
#undef LOADG
#undef STOREB

    if (MODE == 1) {
#pragma unroll
        for (int mi = 0; mi < 4; ++mi)
#pragma unroll
            for (int half = 0; half < 2; ++half) {
                int r = m0 + wm + mi * 16 + grp + half * 8;
                float ds = 0.0f;
#pragma unroll
                for (int ni = 0; ni < 4; ++ni) {
                    int col = n0 + wn + ni * 8 + qd * 2;
                    float v0 = tanhf(acc[mi][ni][half*2+0] + bias[col]);
                    float v1 = tanhf(acc[mi][ni][half*2+1] + bias[col+1]);
                    *(float2*)&Hout[(size_t)r * HH + col] = make_float2(v0, v1);
                    float2 sv = *(const float2*)&S[(size_t)r * HH + col];
                    ds = fmaf(1.0f - v0*v0, sv.x, ds);
                    ds = fmaf(1.0f - v1*v1, sv.y, ds);
                }
                ds += __shfl_xor_sync(0xffffffffu, ds, 1);
                ds += __shfl_xor_sync(0xffffffffu, ds, 2);
                if (qd == 0) atomicAdd(&rowsum[wm + mi*16 + grp + half*8], ds);
            }
        __syncthreads();
        if (tid < 128) atomicAdd(&accd[m0 + tid], wq * rowsum[tid]);
    } else {
#pragma unroll
        for (int mi = 0; mi < 4; ++mi)
#pragma unroll
            for (int half = 0; half < 2; ++half) {
                int r = m0 + wm + mi * 16 + grp + half * 8;
#pragma unroll
                for (int ni = 0; ni < 4; ++ni) {
                    int col = n0 + wn + ni * 8 + qd * 2;
                    float f0 = acc[mi][ni][half*2+0] + bias[col];
                    float f1 = acc[mi][ni][half*2+1] + bias[col+1];
                    size_t idx = (size_t)r * DD + col;
                    float2 az;
                    if (st == 0) az = make_float2(0.f, 0.f);
                    else az = *(float2*)&accz[idx];
                    az.x += wq * f0; az.y += wq * f1;
                    *(float2*)&accz[idx] = az;
                    if (st < 3) {
                        float2 xx = *(const float2*)&x[idx];
                        *(float2*)&z[idx] = make_float2(xx.x + cq*f0, xx.y + cq*f1);
                    }
                }
            }
    }
}

// ---------------- final: out = stack([y0, y1]) ----------------
__global__ __launch_bounds__(256) void final_kernel(const float* __restrict__ x,
                                                    float* __restrict__ out) {
    int i = blockIdx.x * 256 + threadIdx.x;
    const int half = BB * 257;
    if (i >= 2 * half) return;
    if (i < half) {
        int r = i / 257, d = i - r * 257;
        out[i] = (d < 256) ? x[r * DD + d] : 0.0f;
    } else {
        int j = i - half;
        int r = j / 257, d = j - r * 257;
        out[i] = (d < 256) ? x[r * DD + d] + g_accz[r * DD + d] * (1.0f / 6.0f)
                           : -g_accd[r] * (1.0f / 6.0f);
    }
}

// ---------------- launch ----------------
extern "C" void kernel_launch(void* const* d_in, const int* in_sizes, int n_in,
                              void* d_out, int out_size) {
    const float* x  = (const float*)d_in[0];
    const float* W1 = (const float*)d_in[1];
    const float* b1 = (const float*)d_in[2];
    const float* W2 = (const float*)d_in[3];
    const float* b2 = (const float*)d_in[4];
    float* out = (float*)d_out;
    (void)in_sizes; (void)n_in; (void)out_size;

    unsigned int kk[4][2];
    for (unsigned int st = 0; st < 4; ++st) {
        unsigned int f0, f1;
        tf_host(0u, 42u, 0u, st, f0, f1);
        tf_host(f0, f1, 0u, 1u, kk[st][0], kk[st][1]);
    }

    float *gz, *gh, *gbias, *gS, *gaccd, *gaccz;
    cudaGetSymbolAddress((void**)&gz,    g_z);
    cudaGetSymbolAddress((void**)&gh,    g_h);
    cudaGetSymbolAddress((void**)&gbias, g_bias1);
    cudaGetSymbolAddress((void**)&gS,    g_S);
    cudaGetSymbolAddress((void**)&gaccd, g_accd);
    cudaGetSymbolAddress((void**)&gaccz, g_accz);

    cudaFuncSetAttribute(s_kernel, cudaFuncAttributeMaxDynamicSharedMemorySize, SK_SMEM);
    cudaFuncSetAttribute(gemm_kernel<0>, cudaFuncAttributeMaxDynamicSharedMemorySize, GEMM_SMEM);
    cudaFuncSetAttribute(gemm_kernel<1>, cudaFuncAttributeMaxDynamicSharedMemorySize, GEMM_SMEM);

    prep_kernel<<<(DD * HH + 255) / 256, 256>>>(W1, b1, W2);
    for (int st = 0; st < 4; ++st)
        rng_kernel<<<NE / 256, 256>>>(kk[st][0], kk[st][1], st);
    s_kernel<<<dim3(BB / 64, HH / 64, 4), 256, SK_SMEM>>>(W1);

    const float wst[4] = {1.0f, 2.0f, 2.0f, 1.0f};
    const float cst[4] = {0.5f, 0.5f, 1.0f, 0.0f};
    for (int st = 0; st < 4; ++st) {
        const float* Ain = (st == 0) ? x : gz;
        gemm_kernel<1><<<dim3(BB/128, HH/128), 256, GEMM_SMEM>>>(
            Ain, W1, gbias + st*HH, gh,
            gS + (size_t)st * BB * HH, gaccd,
            nullptr, nullptr, nullptr,
            HH, DD, st, wst[st], cst[st]);
        gemm_kernel<0><<<dim3(BB/128, DD/128), 256, GEMM_SMEM>>>(
            gh, W2, b2, nullptr,
            nullptr, nullptr,
            x, gaccz, gz,
            DD, HH, st, wst[st], cst[st]);
    }
    final_kernel<<<(2*BB*257 + 255)/256, 256>>>(x, out);
}